// round 17
// baseline (speedup 1.0000x reference)
#include <cuda_runtime.h>
#include <cuda_fp16.h>
#include <cstdint>

#define BATCH  256
#define MSEL   128
#define DMODEL 2048
#define IFF    5504
#define MN     (MSEL*DMODEL)
#define MI     (MSEL*IFF)

// ---------------- GEMM geometry: BM=128 BN=64 BK=32, single fp16, m16n8k16 ----------------
#define ASTAGE 8192                  // 128 rows * 64B (32 fp16)
#define WSTAGE 4096                  // 32 rows * 128B (64 fp16)
#define STAGEB (ASTAGE + WSTAGE)     // 12288
#define NSTG   4
#define GSMEM  (NSTG*STAGEB)         // 49152

#define SWZ(off)   ((off) ^ (((off) >> 3) & 0x70))   // 128B-row swizzle (W)
#define SWZ64(off) ((off) ^ (((off) >> 3) & 0x30))   // 64B-row swizzle (A)

// ---------------- scratch ----------------
__device__ float g_scores[BATCH];
__device__ int   g_sel[MSEL];
__device__ int   g_rank[BATCH];

__device__ float g_xsel[MSEL*DMODEL];
__device__ float g_x[MSEL*DMODEL];
__device__ float g_part[6*MI];       // 6*MI = 4.23M floats >= 8*MN = 2.10M

__device__ __half g_h[MSEL*DMODEL];
__device__ __half g_v[MSEL*DMODEL];
__device__ __half g_h2[MSEL*DMODEL];
__device__ __half g_a[MSEL*IFF];

// ---------------- helpers ----------------
__device__ __forceinline__ uint32_t s2u(const void* p) {
    uint32_t a;
    asm("{ .reg .u64 t; cvta.to.shared.u64 t, %1; cvt.u32.u64 %0, t; }" : "=r"(a) : "l"(p));
    return a;
}
__device__ __forceinline__ void cpa16(uint32_t dst, const void* src) {
    asm volatile("cp.async.cg.shared.global [%0], [%1], 16;" :: "r"(dst), "l"(src));
}
__device__ __forceinline__ void ldsm4(uint32_t* r, uint32_t a) {
    asm volatile("ldmatrix.sync.aligned.m8n8.x4.shared.b16 {%0,%1,%2,%3},[%4];"
        : "=r"(r[0]),"=r"(r[1]),"=r"(r[2]),"=r"(r[3]) : "r"(a));
}
__device__ __forceinline__ void ldsm4t(uint32_t* r, uint32_t a) {
    asm volatile("ldmatrix.sync.aligned.m8n8.x4.trans.shared.b16 {%0,%1,%2,%3},[%4];"
        : "=r"(r[0]),"=r"(r[1]),"=r"(r[2]),"=r"(r[3]) : "r"(a));
}
__device__ __forceinline__ void mma_f16(float* c, const uint32_t* a, const uint32_t* b) {
    asm volatile("mma.sync.aligned.m16n8k16.row.col.f32.f16.f16.f32 "
        "{%0,%1,%2,%3},{%4,%5,%6,%7},{%8,%9},{%0,%1,%2,%3};"
        : "+f"(c[0]),"+f"(c[1]),"+f"(c[2]),"+f"(c[3])
        : "r"(a[0]),"r"(a[1]),"r"(a[2]),"r"(a[3]),"r"(b[0]),"r"(b[1]));
}

// ---------------- 1. router ----------------
__global__ __launch_bounds__(256) void k_router(const float* __restrict__ hid,
                                                const float* __restrict__ rw,
                                                const float* __restrict__ rb) {
    int b = blockIdx.x, t = threadIdx.x;
    const float4* hp = (const float4*)(hid + (size_t)b * DMODEL);
    const float4* wp = (const float4*)rw;
    float s = 0.f;
    #pragma unroll
    for (int i = 0; i < 2; i++) {
        float4 h = hp[t + i*256], w = wp[t + i*256];
        s += h.x*w.x + h.y*w.y + h.z*w.z + h.w*w.w;
    }
    __shared__ float red[256];
    red[t] = s; __syncthreads();
    for (int o = 128; o > 0; o >>= 1) { if (t < o) red[t] += red[t+o]; __syncthreads(); }
    if (t == 0) g_scores[b] = red[0] + rb[0];
}

// ---------------- 2. top-k (rank counting) ----------------
__global__ __launch_bounds__(256) void k_select() {
    __shared__ float sc[BATCH];
    int t = threadIdx.x;
    sc[t] = g_scores[t];
    __syncthreads();
    float mine = sc[t];
    int r = 0;
    #pragma unroll 8
    for (int j = 0; j < BATCH; j++) {
        float v = sc[j];
        if (v > mine || (v == mine && j < t)) r++;
    }
    if (r < MSEL) { g_rank[t] = r; g_sel[r] = t; }
    else          { g_rank[t] = -1; }
}

// ---------------- 3. RMS -> fp16 ----------------
template<int MODE>
__global__ __launch_bounds__(256) void k_rms(const float* __restrict__ src,
                                             const float* __restrict__ w) {
    int i = blockIdx.x, t = threadIdx.x;
    int row = (MODE == 0) ? g_sel[i] : i;
    const float* base = (MODE == 0) ? src : g_x;
    const float4* s4 = (const float4*)(base + (size_t)row * DMODEL);
    const float4* w4 = (const float4*)w;

    float4 v0 = s4[t], v1 = s4[t + 256];
    float ss = v0.x*v0.x + v0.y*v0.y + v0.z*v0.z + v0.w*v0.w
             + v1.x*v1.x + v1.y*v1.y + v1.z*v1.z + v1.w*v1.w;
    __shared__ float red[256];
    red[t] = ss; __syncthreads();
    for (int o = 128; o > 0; o >>= 1) { if (t < o) red[t] += red[t+o]; __syncthreads(); }
    __shared__ float rs_sh;
    if (t == 0) rs_sh = rsqrtf(red[0] * (1.0f/DMODEL) + 1e-6f);
    __syncthreads();
    float rs = rs_sh;

    if (MODE == 0) {
        float4* xo = (float4*)(g_xsel + (size_t)i * DMODEL);
        xo[t] = v0; xo[t + 256] = v1;
    }
    __half* hh = (MODE == 0) ? g_h : g_h2;
    size_t o0 = (size_t)i * DMODEL + 4*t;
    size_t o1 = o0 + 1024;
    float4 w0 = w4[t], w1 = w4[t + 256];
    hh[o0+0] = __float2half_rn(v0.x * rs * w0.x);
    hh[o0+1] = __float2half_rn(v0.y * rs * w0.y);
    hh[o0+2] = __float2half_rn(v0.z * rs * w0.z);
    hh[o0+3] = __float2half_rn(v0.w * rs * w0.w);
    hh[o1+0] = __float2half_rn(v1.x * rs * w1.x);
    hh[o1+1] = __float2half_rn(v1.y * rs * w1.y);
    hh[o1+2] = __float2half_rn(v1.z * rs * w1.z);
    hh[o1+3] = __float2half_rn(v1.w * rs * w1.w);
}

// ---------------- 4. GEMM: single fp16, mma.sync, swizzled smem, 4-stage cp.async ---------
// C[128,N] = A[128,K] @ W[K,N].
// which: 0 h@wv->part[s]  1 v@wo->part[s]  2 h2@{wg,wu}->part {s, 3+s}  3 a@wd->part[s]
__global__ __launch_bounds__(256, 3) void k_gemm8(int which,
                                                  const float* __restrict__ W0,
                                                  const float* __restrict__ W1,
                                                  int ntiles0, int Nld, int K,
                                                  int kchunk) {
    extern __shared__ __align__(16) char smem[];
    uint32_t sb = s2u(smem);
    int t = threadIdx.x;
    int lane = t & 31, warp = t >> 5;
    int wm = warp & 3, wn = warp >> 2;

    int tile = blockIdx.x, s = blockIdx.y;
    const __half* A;
    float* C;
    const float* W = W0;
    if (which == 0)      { A = g_h;  C = g_part + (size_t)s * MN; }
    else if (which == 1) { A = g_v;  C = g_part + (size_t)s * MN; }
    else if (which == 2) {
        A = g_h2;
        if (tile >= ntiles0) { W = W1; tile -= ntiles0; C = g_part + (size_t)(3 + s) * MI; }
        else                 { C = g_part + (size_t)s * MI; }
    }
    else                 { A = g_a;  C = g_part + (size_t)s * MN; }

    int n0 = tile * 64;
    int kbeg = s * kchunk;
    int kend = kbeg + kchunk; if (kend > K) kend = K;
    int niter = (kend - kbeg) >> 5;

    // W fill mapping: 32 k-rows, 8 threads/row, 8 fp32 each
    int wk = t >> 3, wc = (t & 7) * 8;
    const float* Wg = W + (size_t)(kbeg + wk) * Nld + n0 + wc;

    float acc[2][4][4];
    #pragma unroll
    for (int i = 0; i < 2; i++)
        #pragma unroll
        for (int j = 0; j < 4; j++)
            #pragma unroll
            for (int q = 0; q < 4; q++) acc[i][j][q] = 0.f;

    float wreg[2][8];

    auto LOAD_A = [&](int it) {
        uint32_t stg = sb + (uint32_t)(it & 3) * STAGEB;
        int k0 = kbeg + (it << 5);
        #pragma unroll
        for (int c = 0; c < 2; c++) {
            int idx = c * 256 + t;
            int m = idx >> 2, j = idx & 3;      // row, 16B chunk within 64B row
            const __half* src = A + (size_t)m * K + k0 + j * 8;
            cpa16(stg + SWZ64((uint32_t)(m * 64 + j * 16)), src);
        }
        asm volatile("cp.async.commit_group;" ::: "memory");
    };
    auto LDG_W = [&](int it, int buf) {
        const float* p = Wg + (size_t)(it << 5) * Nld;
        float4 a = *(const float4*)p, b = *(const float4*)(p + 4);
        wreg[buf][0]=a.x; wreg[buf][1]=a.y; wreg[buf][2]=a.z; wreg[buf][3]=a.w;
        wreg[buf][4]=b.x; wreg[buf][5]=b.y; wreg[buf][6]=b.z; wreg[buf][7]=b.w;
    };
    auto STS_W = [&](int it, int buf) {
        uint32_t stg = sb + (uint32_t)(it & 3) * STAGEB + ASTAGE;
        uint32_t off = SWZ((uint32_t)(wk * 128 + wc * 2));
        uint32_t h[4];
        #pragma unroll
        for (int j = 0; j < 4; j++)
            asm("cvt.rn.f16x2.f32 %0, %1, %2;" : "=r"(h[j]) : "f"(wreg[buf][2*j+1]), "f"(wreg[buf][2*j]));
        asm volatile("st.shared.v4.b32 [%0], {%1,%2,%3,%4};"
            :: "r"(stg + off), "r"(h[0]), "r"(h[1]), "r"(h[2]), "r"(h[3]) : "memory");
    };

    int lrow = ((lane >> 3) & 1) * 8 + (lane & 7);
    int lseg = lane >> 4;

    auto DOMMA = [&](int it) {
        uint32_t stg = sb + (uint32_t)(it & 3) * STAGEB;
        uint32_t bw = stg + ASTAGE;
        #pragma unroll
        for (int ks = 0; ks < 2; ks++) {
            uint32_t af[2][4];
            #pragma unroll
            for (int mt = 0; mt < 2; mt++) {
                int m = wm * 32 + mt * 16 + lrow;
                ldsm4(af[mt], stg + SWZ64((uint32_t)(m * 64 + (ks * 2 + lseg) * 16)));
            }
            uint32_t bf[2][4];
            #pragma unroll
            for (int ntile = 0; ntile < 2; ntile++) {
                int kr = ks * 16 + lrow;
                uint32_t bd = SWZ((uint32_t)(kr * 128 + (wn * 32 + ntile * 16 + lseg * 8) * 2));
                ldsm4t(bf[ntile], bw + bd);
            }
            #pragma unroll
            for (int mt = 0; mt < 2; mt++)
                #pragma unroll
                for (int nt = 0; nt < 4; nt++)
                    mma_f16(acc[mt][nt], af[mt], &bf[nt >> 1][(nt & 1) * 2]);
        }
    };

    // ---- prologue: W stage0 in smem; A stages 0..2 in flight; W 1,2 in regs ----
    LDG_W(0, 0); STS_W(0, 0);
    LOAD_A(0);
    if (niter > 1) { LDG_W(1, 1); LOAD_A(1); }
    if (niter > 2) { LDG_W(2, 0); LOAD_A(2); }

    for (int it = 0; it < niter; it++) {
        // wait until stage `it` has landed (keep up to 2 younger groups in flight)
        if (it + 2 < niter)      asm volatile("cp.async.wait_group 2;" ::: "memory");
        else if (it + 1 < niter) asm volatile("cp.async.wait_group 1;" ::: "memory");
        else                     asm volatile("cp.async.wait_group 0;" ::: "memory");
        __syncthreads();
        if (it + 1 < niter) STS_W(it + 1, (it + 1) & 1);
        if (it + 3 < niter) { LOAD_A(it + 3); LDG_W(it + 3, (it + 3) & 1); }
        DOMMA(it);
    }

    // ---- epilogue: fp32 partials ----
    int r0 = wm * 32 + (lane >> 2);
    int cb = n0 + wn * 32 + (lane & 3) * 2;
    #pragma unroll
    for (int mt = 0; mt < 2; mt++)
        #pragma unroll
        for (int nt = 0; nt < 4; nt++) {
            float* p = C + (size_t)(r0 + mt * 16) * Nld + cb + nt * 8;
            *(float2*)p = make_float2(acc[mt][nt][0], acc[mt][nt][1]);
            *(float2*)(p + 8 * (size_t)Nld) = make_float2(acc[mt][nt][2], acc[mt][nt][3]);
        }
}

// ---------------- epilogues (8-way split-K reduce for D-major GEMMs) ----------------
__global__ __launch_bounds__(256) void k_epi_v(const float* __restrict__ bias) {
    int idx = blockIdx.x * 256 + threadIdx.x;
    float v = bias[idx & (DMODEL - 1)];
    #pragma unroll
    for (int p = 0; p < 8; p++) v += g_part[idx + (size_t)p*MN];
    g_v[idx] = __float2half_rn(v);
}

__global__ __launch_bounds__(256) void k_epi_x() {
    int idx = blockIdx.x * 256 + threadIdx.x;
    float v = g_xsel[idx];
    #pragma unroll
    for (int p = 0; p < 8; p++) v += g_part[idx + (size_t)p*MN];
    g_x[idx] = v;
}

__global__ __launch_bounds__(256) void k_epi_act() {
    int idx = blockIdx.x * 256 + threadIdx.x;
    float g = g_part[idx] + g_part[idx + (size_t)MI] + g_part[idx + (size_t)2*MI];
    float u = g_part[idx + (size_t)3*MI] + g_part[idx + (size_t)4*MI] + g_part[idx + (size_t)5*MI];
    float a = g * (1.0f / (1.0f + expf(-g))) * u;
    g_a[idx] = __float2half_rn(a);
}

// ---------------- final scatter ----------------
__global__ __launch_bounds__(256) void k_final(const float* __restrict__ hid,
                                               float* __restrict__ out) {
    int b = blockIdx.x, t = threadIdx.x;
    int r = g_rank[b];
    if (r < 0) {
        const float4* s = (const float4*)(hid + (size_t)b * DMODEL);
        float4*       o = (float4*)(out + (size_t)b * DMODEL);
        o[t] = s[t];
        o[t + 256] = s[t + 256];
    } else {
        const float* xr = g_x + (size_t)r * DMODEL;
        const float* p  = g_part + (size_t)r * DMODEL;
        float* o = out + (size_t)b * DMODEL;
        #pragma unroll
        for (int c = 0; c < 8; c++) {
            int i = t + c * 256;
            float v = xr[i];
            #pragma unroll
            for (int q = 0; q < 8; q++) v += p[i + (size_t)q*MN];
            o[i] = v;
        }
    }
}

// ---------------- launch ----------------
extern "C" void kernel_launch(void* const* d_in, const int* in_sizes, int n_in,
                              void* d_out, int out_size) {
    const float* hid = (const float*)d_in[0];
    const float* rw  = (const float*)d_in[3];
    const float* rb  = (const float*)d_in[4];
    const float* ln1 = (const float*)d_in[5];
    const float* ln2 = (const float*)d_in[6];
    const float* wv  = (const float*)d_in[11];
    const float* bv  = (const float*)d_in[12];
    const float* wo  = (const float*)d_in[13];
    const float* wg  = (const float*)d_in[14];
    const float* wu  = (const float*)d_in[15];
    const float* wd  = (const float*)d_in[16];
    float* out = (float*)d_out;

    static bool attr_set = false;
    if (!attr_set) {
        cudaFuncSetAttribute(k_gemm8, cudaFuncAttributeMaxDynamicSharedMemorySize, GSMEM);
        attr_set = true;
    }

    k_router<<<BATCH, 256>>>(hid, rw, rb);
    k_select<<<1, 256>>>();
    k_rms<0><<<MSEL, 256>>>(hid, ln1);

    // v = h @ wv (+bv): split-K=8, kchunk=256 (8*256 = 2048 exact)
    k_gemm8<<<dim3(32, 8), 256, GSMEM>>>(0, wv, nullptr, 32, DMODEL, DMODEL, 256);
    k_epi_v<<<MN / 256, 256>>>(bv);

    // o = v @ wo ; x = x_sel + o
    k_gemm8<<<dim3(32, 8), 256, GSMEM>>>(1, wo, nullptr, 32, DMODEL, DMODEL, 256);
    k_epi_x<<<MN / 256, 256>>>();

    k_rms<1><<<MSEL, 256>>>(nullptr, ln2);

    // gate & up fused, split-K=3: kchunk=704 (slabs 704/704/640 — covers 2048)
    k_gemm8<<<dim3(172, 3), 256, GSMEM>>>(2, wg, wu, 86, IFF, DMODEL, 704);
    k_epi_act<<<MI / 256, 256>>>();

    // down: K=5504, split-K=8, kchunk=704 (slabs 0..6: 704, slab 7: 576 — covers 5504)
    k_gemm8<<<dim3(32, 8), 256, GSMEM>>>(3, wd, nullptr, 32, DMODEL, IFF, 704);

    k_final<<<BATCH, 256>>>(hid, out);
}